// round 4
// baseline (speedup 1.0000x reference)
#include <cuda_runtime.h>
#include <cuda_bf16.h>
#include <math.h>

#define Bsz 2
#define S 2048
#define D 1024
#define H 16
#define KV 8
#define HD 64
#define WINDOW 512
#define M_TOT (Bsz * S)      // 4096

// Scratch (device globals; no allocation allowed)
__device__ float g_Q[M_TOT * (H * HD)];    // [b*s, 1024]
__device__ float g_K[M_TOT * (KV * HD)];   // [b*s, 512]
__device__ float g_V[M_TOT * (KV * HD)];   // [b*s, 512]
__device__ float g_O[M_TOT * (H * HD)];    // [b*s, 1024]

// ---------------------------------------------------------------------------
// Kernel 1: fused QKV GEMM + RoPE epilogue.
// C = X (4096x1024) @ [Wq | Wk | Wv] (1024 x 2048), 64x64 tiles.
// Column blocks: [0,1024) -> Q heads, [1024,1536) -> K heads, [1536,2048) -> V.
// ---------------------------------------------------------------------------
__global__ __launch_bounds__(256) void qkv_rope_kernel(
    const float* __restrict__ X,
    const float* __restrict__ Wq,
    const float* __restrict__ Wk,
    const float* __restrict__ Wv)
{
    __shared__ float As[16][64];
    __shared__ float Bs[16][64];
    __shared__ float Cs[64][65];

    const int nb = blockIdx.x;          // 0..31
    const int mb = blockIdx.y;          // 0..63
    const int gc0 = nb * 64;

    const float* Bp; int ldb, bcol0;
    if (gc0 < 1024)      { Bp = Wq; ldb = 1024; bcol0 = gc0; }
    else if (gc0 < 1536) { Bp = Wk; ldb = 512;  bcol0 = gc0 - 1024; }
    else                 { Bp = Wv; ldb = 512;  bcol0 = gc0 - 1536; }

    const int tid = threadIdx.x;
    const int tx = tid & 15;
    const int ty = tid >> 4;

    float acc[4][4];
#pragma unroll
    for (int i = 0; i < 4; i++)
#pragma unroll
        for (int j = 0; j < 4; j++) acc[i][j] = 0.f;

    const int arow = tid >> 2;          // 0..63
    const int ak   = (tid & 3) * 4;     // 0,4,8,12
    const int brow = tid >> 4;          // 0..15
    const int bcol = (tid & 15) * 4;    // 0..60

    const float* Ag = X + (size_t)(mb * 64 + arow) * 1024;

    for (int k0 = 0; k0 < 1024; k0 += 16) {
        float4 a4 = *(const float4*)(Ag + k0 + ak);
        As[ak + 0][arow] = a4.x;
        As[ak + 1][arow] = a4.y;
        As[ak + 2][arow] = a4.z;
        As[ak + 3][arow] = a4.w;
        float4 b4 = *(const float4*)(Bp + (size_t)(k0 + brow) * ldb + bcol0 + bcol);
        *(float4*)&Bs[brow][bcol] = b4;
        __syncthreads();
#pragma unroll
        for (int k = 0; k < 16; k++) {
            float a[4], b[4];
#pragma unroll
            for (int i = 0; i < 4; i++) a[i] = As[k][ty * 4 + i];
#pragma unroll
            for (int j = 0; j < 4; j++) b[j] = Bs[k][tx * 4 + j];
#pragma unroll
            for (int i = 0; i < 4; i++)
#pragma unroll
                for (int j = 0; j < 4; j++) acc[i][j] += a[i] * b[j];
        }
        __syncthreads();
    }

    // stage to shared for RoPE (needs paired columns d and d±32)
#pragma unroll
    for (int i = 0; i < 4; i++)
#pragma unroll
        for (int j = 0; j < 4; j++)
            Cs[ty * 4 + i][tx * 4 + j] = acc[i][j];
    __syncthreads();

    const bool isQ = (gc0 < 1024);
    const bool isK = (gc0 >= 1024) && (gc0 < 1536);

    for (int lin = tid; lin < 64 * 64; lin += 256) {
        const int r = lin >> 6;
        const int d = lin & 63;
        const int gm = mb * 64 + r;
        float val = Cs[r][d];
        if (isQ || isK) {
            const int t = gm & (S - 1);
            const int f = d & 31;
            const float invf = expf(-logf(10000.0f) * (float)f * (1.0f / 32.0f));
            const float ang = (float)t * invf;
            float cv, sv;
            sincosf(ang, &sv, &cv);
            const float rot = (d < 32) ? -Cs[r][d + 32] : Cs[r][d - 32];
            val = val * cv + rot * sv;
        }
        if (isQ)       g_Q[(size_t)gm * 1024 + gc0 + d] = val;
        else if (isK)  g_K[(size_t)gm * 512 + (gc0 - 1024) + d] = val;
        else           g_V[(size_t)gm * 512 + (gc0 - 1536) + d] = val;
    }
}

// ---------------------------------------------------------------------------
// Kernel 2: sliding-window causal attention, flash-style online softmax, fp32.
// grid = (S/64, B*H), 128 threads. Query tile 64, key tile 32.
// Thread (r = tid>>1, hc = tid&1): owns query row r; scores for 16 keys;
// output dims [hc*32, hc*32+32).
// ---------------------------------------------------------------------------
__global__ __launch_bounds__(128) void attn_kernel()
{
    __shared__ float Qs[64][65];
    __shared__ float KVs[32][65];
    __shared__ float Ps[64][65];

    const int bh = blockIdx.y;
    const int b = bh >> 4;
    const int h = bh & 15;
    const int kvh = h >> 1;          // n_rep = 2
    const int q0 = blockIdx.x * 64;

    const int tid = threadIdx.x;
    const int r = tid >> 1;
    const int hc = tid & 1;
    const int i = q0 + r;            // global query index

    const float* Qg = g_Q + ((size_t)(b * S + q0)) * 1024 + h * 64;
    for (int lin = tid; lin < 64 * 64; lin += 128) {
        int rr = lin >> 6, k = lin & 63;
        Qs[rr][k] = Qg[(size_t)rr * 1024 + k];
    }

    float o[32];
#pragma unroll
    for (int d = 0; d < 32; d++) o[d] = 0.f;
    float m = -1e30f, l = 0.f;

    const int t0 = max(0, q0 - WINDOW) >> 5;
    const int t1 = (q0 >> 5) + 1;

    const float* Kg = g_K + ((size_t)b * S) * 512 + kvh * 64;
    const float* Vg = g_V + ((size_t)b * S) * 512 + kvh * 64;

    __syncthreads();

    for (int t = t0; t <= t1; t++) {
        const int j0 = t << 5;

        // load K tile (32 keys x 64 dims)
        for (int lin = tid; lin < 32 * 64; lin += 128) {
            int c = lin >> 6, k = lin & 63;
            KVs[c][k] = Kg[(size_t)(j0 + c) * 512 + k];
        }
        __syncthreads();

        float s[16];
#pragma unroll
        for (int c = 0; c < 16; c++) s[c] = 0.f;
        for (int k = 0; k < 64; k++) {
            const float qv = Qs[r][k];
#pragma unroll
            for (int c = 0; c < 16; c++) s[c] += qv * KVs[hc * 16 + c][k];
        }

        float tmax = -1e30f;
#pragma unroll
        for (int c = 0; c < 16; c++) {
            const int j = j0 + hc * 16 + c;
            const bool ok = (j <= i) && (j >= i - WINDOW);
            s[c] = ok ? s[c] * 0.125f : -1e30f;
            tmax = fmaxf(tmax, s[c]);
        }
        tmax = fmaxf(tmax, __shfl_xor_sync(0xffffffffu, tmax, 1));
        const float mnew = fmaxf(m, tmax);
        const float scale = __expf(m - mnew);

        float psum = 0.f;
#pragma unroll
        for (int c = 0; c < 16; c++) {
            const float p = (s[c] > -1e29f) ? __expf(s[c] - mnew) : 0.f;
            Ps[r][hc * 16 + c] = p;
            psum += p;
        }
        l = l * scale + psum;
        m = mnew;
#pragma unroll
        for (int d = 0; d < 32; d++) o[d] *= scale;

        __syncthreads();   // scores done reading K; Ps written

        // load V tile over K
        for (int lin = tid; lin < 32 * 64; lin += 128) {
            int c = lin >> 6, k = lin & 63;
            KVs[c][k] = Vg[(size_t)(j0 + c) * 512 + k];
        }
        __syncthreads();

#pragma unroll 4
        for (int c = 0; c < 32; c++) {
            const float p = Ps[r][c];
#pragma unroll
            for (int d = 0; d < 32; d++) o[d] += p * KVs[c][hc * 32 + d];
        }
        __syncthreads();   // before next tile overwrites KVs / Ps
    }

    float ltot = l + __shfl_xor_sync(0xffffffffu, l, 1);
    const float inv = 1.f / ltot;
    float* Og = g_O + ((size_t)(b * S + i)) * 1024 + h * 64 + hc * 32;
#pragma unroll
    for (int d = 0; d < 32; d++) Og[d] = o[d] * inv;
}

// ---------------------------------------------------------------------------
// Kernel 3: output projection: out = g_O (4096x1024) @ Wo (1024x1024)
// ---------------------------------------------------------------------------
__global__ __launch_bounds__(256) void outproj_kernel(
    const float* __restrict__ Wo, float* __restrict__ out)
{
    __shared__ float As[16][64];
    __shared__ float Bs[16][64];

    const int nb = blockIdx.x;   // 0..15
    const int mb = blockIdx.y;   // 0..63
    const int gc0 = nb * 64;

    const int tid = threadIdx.x;
    const int tx = tid & 15;
    const int ty = tid >> 4;

    float acc[4][4];
#pragma unroll
    for (int i = 0; i < 4; i++)
#pragma unroll
        for (int j = 0; j < 4; j++) acc[i][j] = 0.f;

    const int arow = tid >> 2;
    const int ak   = (tid & 3) * 4;
    const int brow = tid >> 4;
    const int bcol = (tid & 15) * 4;

    const float* Ag = g_O + (size_t)(mb * 64 + arow) * 1024;

    for (int k0 = 0; k0 < 1024; k0 += 16) {
        float4 a4 = *(const float4*)(Ag + k0 + ak);
        As[ak + 0][arow] = a4.x;
        As[ak + 1][arow] = a4.y;
        As[ak + 2][arow] = a4.z;
        As[ak + 3][arow] = a4.w;
        float4 b4 = *(const float4*)(Wo + (size_t)(k0 + brow) * 1024 + gc0 + bcol);
        *(float4*)&Bs[brow][bcol] = b4;
        __syncthreads();
#pragma unroll
        for (int k = 0; k < 16; k++) {
            float a[4], bb[4];
#pragma unroll
            for (int i = 0; i < 4; i++) a[i] = As[k][ty * 4 + i];
#pragma unroll
            for (int j = 0; j < 4; j++) bb[j] = Bs[k][tx * 4 + j];
#pragma unroll
            for (int i = 0; i < 4; i++)
#pragma unroll
                for (int j = 0; j < 4; j++) acc[i][j] += a[i] * bb[j];
        }
        __syncthreads();
    }

#pragma unroll
    for (int i = 0; i < 4; i++) {
        const int gm = mb * 64 + ty * 4 + i;
#pragma unroll
        for (int j = 0; j < 4; j++) {
            out[(size_t)gm * 1024 + gc0 + tx * 4 + j] = acc[i][j];
        }
    }
}

extern "C" void kernel_launch(void* const* d_in, const int* in_sizes, int n_in,
                              void* d_out, int out_size)
{
    const float* X  = (const float*)d_in[0];
    const float* Wq = (const float*)d_in[1];
    const float* Wk = (const float*)d_in[2];
    const float* Wv = (const float*)d_in[3];
    const float* Wo = (const float*)d_in[4];
    float* out = (float*)d_out;

    qkv_rope_kernel<<<dim3(32, 64), 256>>>(X, Wq, Wk, Wv);
    attn_kernel<<<dim3(S / 64, Bsz * H), 128>>>();
    outproj_kernel<<<dim3(16, 64), 256>>>(Wo, out);
}

// round 5
// speedup vs baseline: 1.4468x; 1.4468x over previous
#include <cuda_runtime.h>
#include <cuda_bf16.h>
#include <math.h>
#include <stdint.h>

#define Bsz 2
#define S 2048
#define H 16
#define KV 8
#define HD 64
#define WINDOW 512
#define M_TOT (Bsz * S)      // 4096

__device__ float g_Q[M_TOT * (H * HD)];    // [b*s, 1024]
__device__ float g_K[M_TOT * (KV * HD)];   // [b*s, 512]
__device__ float g_V[M_TOT * (KV * HD)];
__device__ float g_O[M_TOT * (H * HD)];
__device__ float2 g_rope[S * 32];          // (cos,sin) per (t,f)

__device__ __forceinline__ uint32_t f2tf(float f) {
    uint32_t r;
    asm("cvt.rna.tf32.f32 %0, %1;" : "=r"(r) : "f"(f));
    return r;
}

__device__ __forceinline__ void mma_tf32(float c[4],
    uint32_t a0, uint32_t a1, uint32_t a2, uint32_t a3, uint32_t b0, uint32_t b1) {
    asm volatile(
        "mma.sync.aligned.m16n8k8.row.col.f32.tf32.tf32.f32 "
        "{%0,%1,%2,%3}, {%4,%5,%6,%7}, {%8,%9}, {%0,%1,%2,%3};"
        : "+f"(c[0]), "+f"(c[1]), "+f"(c[2]), "+f"(c[3])
        : "r"(a0), "r"(a1), "r"(a2), "r"(a3), "r"(b0), "r"(b1));
}

// ---------------------------------------------------------------------------
// RoPE table + in-place apply (identical math to previous passing kernel)
// ---------------------------------------------------------------------------
__global__ void rope_init_kernel() {
    const int idx = blockIdx.x * 256 + threadIdx.x;  // 65536
    const int t = idx >> 5, f = idx & 31;
    const float invf = expf(-logf(10000.0f) * (float)f * (1.0f / 32.0f));
    float sv, cv;
    sincosf((float)t * invf, &sv, &cv);
    g_rope[idx] = make_float2(cv, sv);
}

// pairs: Q has 4096*512, K has 4096*256. grid covers both.
__global__ __launch_bounds__(256) void rope_apply_kernel() {
    const int idx = blockIdx.x * 256 + threadIdx.x;
    float* buf; int ld, p;
    if (idx < M_TOT * 512) { buf = g_Q; ld = 1024; p = idx; }
    else                   { buf = g_K; ld = 512;  p = idx - M_TOT * 512; }
    const int pph = ld >> 1;             // pairs per row: 512 or 256
    const int row = p / pph;
    const int q = p - row * pph;
    const int h = q >> 5, f = q & 31;
    const int t = row & (S - 1);
    float* base = buf + (size_t)row * ld + h * 64 + f;
    const float x = base[0], y = base[32];
    const float2 cs = g_rope[t * 32 + f];
    base[0]  = x * cs.x - y * cs.y;
    base[32] = y * cs.x + x * cs.y;
}

// ---------------------------------------------------------------------------
// tf32 GEMM core: 128x128 block tile, BK=16, 256 thr = 8 warps (2M x 4N).
// smem pair layout: sA[st][kc][m*4+c] = (A[m][c], A[m][c+4])  (c = k within chunk)
//                   sB[st][kc][n*4+c] = (B[c][n], B[c+4][n])
// Fragment loads become LDS.64 at [base + lane]: conflict-free, no swizzle.
// ---------------------------------------------------------------------------
__device__ __forceinline__ void gemm_tf32_core(
    const float* __restrict__ A0,   // &A[mrow0][0], lda=1024, K=1024
    const float* __restrict__ Bp, int ldb, int colbase,
    uint2 (*sA)[2][512], uint2 (*sB)[2][512],
    float c[4][4][4])
{
    const int tid = threadIdx.x, lane = tid & 31, warp = tid >> 5;
    const int wm = warp >> 2, wn = warp & 3;

#pragma unroll
    for (int m = 0; m < 4; m++)
#pragma unroll
        for (int n = 0; n < 4; n++)
#pragma unroll
            for (int q = 0; q < 4; q++) c[m][n][q] = 0.f;

    // A loader: m = tid>>1, kc = tid&1
    const int am = tid >> 1, akc = tid & 1;
    const float* ap = A0 + (size_t)am * 1024 + akc * 8;
    // B loader: c = tid&3, kc = (tid>>2)&1, ngrp = tid>>3
    const int bc = tid & 3, bkc = (tid >> 2) & 1, bn = (tid >> 3) * 4;
    const float* bp = Bp + (size_t)(bkc * 8 + bc) * ldb + colbase + bn;

    float la[8], lb[8];
#define LOAD_G(k0) do { \
        float4 a0_ = *(const float4*)(ap + (k0)); \
        float4 a1_ = *(const float4*)(ap + (k0) + 4); \
        la[0]=a0_.x; la[1]=a0_.y; la[2]=a0_.z; la[3]=a0_.w; \
        la[4]=a1_.x; la[5]=a1_.y; la[6]=a1_.z; la[7]=a1_.w; \
        float4 b0_ = *(const float4*)(bp + (size_t)(k0) * ldb); \
        float4 b1_ = *(const float4*)(bp + (size_t)((k0) + 4) * ldb); \
        lb[0]=b0_.x; lb[1]=b0_.y; lb[2]=b0_.z; lb[3]=b0_.w; \
        lb[4]=b1_.x; lb[5]=b1_.y; lb[6]=b1_.z; lb[7]=b1_.w; \
    } while (0)
#define STS_T(st) do { \
        uint2* a_ = sA[st][akc] + am * 4; \
        a_[0] = make_uint2(f2tf(la[0]), f2tf(la[4])); \
        a_[1] = make_uint2(f2tf(la[1]), f2tf(la[5])); \
        a_[2] = make_uint2(f2tf(la[2]), f2tf(la[6])); \
        a_[3] = make_uint2(f2tf(la[3]), f2tf(la[7])); \
        uint2* b_ = sB[st][bkc]; \
        b_[(bn + 0) * 4 + bc] = make_uint2(f2tf(lb[0]), f2tf(lb[4])); \
        b_[(bn + 1) * 4 + bc] = make_uint2(f2tf(lb[1]), f2tf(lb[5])); \
        b_[(bn + 2) * 4 + bc] = make_uint2(f2tf(lb[2]), f2tf(lb[6])); \
        b_[(bn + 3) * 4 + bc] = make_uint2(f2tf(lb[3]), f2tf(lb[7])); \
    } while (0)

    LOAD_G(0);
    STS_T(0);
    __syncthreads();

    for (int kt = 0; kt < 64; kt++) {
        const int st = kt & 1;
        if (kt < 63) LOAD_G((kt + 1) * 16);
#pragma unroll
        for (int kc = 0; kc < 2; kc++) {
            const uint2* a = sA[st][kc];
            const uint2* b = sB[st][kc];
            uint2 alo[4], ahi[4], bf[4];
#pragma unroll
            for (int m = 0; m < 4; m++) {
                alo[m] = a[wm * 256 + m * 64 + lane];
                ahi[m] = a[wm * 256 + m * 64 + 32 + lane];
            }
#pragma unroll
            for (int n = 0; n < 4; n++)
                bf[n] = b[wn * 128 + n * 32 + lane];
#pragma unroll
            for (int m = 0; m < 4; m++)
#pragma unroll
                for (int n = 0; n < 4; n++)
                    mma_tf32(c[m][n], alo[m].x, ahi[m].x, alo[m].y, ahi[m].y,
                             bf[n].x, bf[n].y);
        }
        if (kt < 63) STS_T(st ^ 1);
        __syncthreads();
    }
#undef LOAD_G
#undef STS_T
}

__device__ __forceinline__ void gemm_store(
    float* dst, int dld, int mrow0, int colbase, float c[4][4][4])
{
    const int lane = threadIdx.x & 31, warp = threadIdx.x >> 5;
    const int wm = warp >> 2, wn = warp & 3;
#pragma unroll
    for (int m = 0; m < 4; m++) {
        const int r0 = mrow0 + wm * 64 + m * 16 + (lane >> 2);
#pragma unroll
        for (int n = 0; n < 4; n++) {
            const int gc = colbase + wn * 32 + n * 8 + 2 * (lane & 3);
            *(float2*)&dst[(size_t)r0 * dld + gc]       = make_float2(c[m][n][0], c[m][n][1]);
            *(float2*)&dst[(size_t)(r0 + 8) * dld + gc] = make_float2(c[m][n][2], c[m][n][3]);
        }
    }
}

// grid (16, 32): bx<8 -> Q, 8..11 -> K, 12..15 -> V
__global__ __launch_bounds__(256) void qkv_tf32_kernel(
    const float* __restrict__ X, const float* __restrict__ Wq,
    const float* __restrict__ Wk, const float* __restrict__ Wv)
{
    __shared__ uint2 sA[2][2][512];
    __shared__ uint2 sB[2][2][512];
    const int bx = blockIdx.x;
    const int mrow0 = blockIdx.y * 128;
    const float* Bp; int ldb; float* dst; int dld; int colbase;
    if (bx < 8)       { Bp = Wq; ldb = 1024; dst = g_Q; dld = 1024; colbase = bx * 128; }
    else if (bx < 12) { Bp = Wk; ldb = 512;  dst = g_K; dld = 512;  colbase = (bx - 8) * 128; }
    else              { Bp = Wv; ldb = 512;  dst = g_V; dld = 512;  colbase = (bx - 12) * 128; }
    float c[4][4][4];
    gemm_tf32_core(X + (size_t)mrow0 * 1024, Bp, ldb, colbase, sA, sB, c);
    gemm_store(dst, dld, mrow0, colbase, c);
}

__global__ __launch_bounds__(256) void outproj_tf32_kernel(
    const float* __restrict__ Wo, float* __restrict__ out)
{
    __shared__ uint2 sA[2][2][512];
    __shared__ uint2 sB[2][2][512];
    const int colbase = blockIdx.x * 128;
    const int mrow0 = blockIdx.y * 128;
    float c[4][4][4];
    gemm_tf32_core(g_O + (size_t)mrow0 * 1024, Wo, 1024, colbase, sA, sB, c);
    gemm_store(out, 1024, mrow0, colbase, c);
}

// ---------------------------------------------------------------------------
// Attention (unchanged from passing R0 kernel)
// ---------------------------------------------------------------------------
__global__ __launch_bounds__(128) void attn_kernel()
{
    __shared__ float Qs[64][65];
    __shared__ float KVs[32][65];
    __shared__ float Ps[64][65];

    const int bh = blockIdx.y;
    const int b = bh >> 4;
    const int h = bh & 15;
    const int kvh = h >> 1;
    const int q0 = blockIdx.x * 64;

    const int tid = threadIdx.x;
    const int r = tid >> 1;
    const int hc = tid & 1;
    const int i = q0 + r;

    const float* Qg = g_Q + ((size_t)(b * S + q0)) * 1024 + h * 64;
    for (int lin = tid; lin < 64 * 64; lin += 128) {
        int rr = lin >> 6, k = lin & 63;
        Qs[rr][k] = Qg[(size_t)rr * 1024 + k];
    }

    float o[32];
#pragma unroll
    for (int d = 0; d < 32; d++) o[d] = 0.f;
    float m = -1e30f, l = 0.f;

    const int t0 = max(0, q0 - WINDOW) >> 5;
    const int t1 = (q0 >> 5) + 1;

    const float* Kg = g_K + ((size_t)b * S) * 512 + kvh * 64;
    const float* Vg = g_V + ((size_t)b * S) * 512 + kvh * 64;

    __syncthreads();

    for (int t = t0; t <= t1; t++) {
        const int j0 = t << 5;
        for (int lin = tid; lin < 32 * 64; lin += 128) {
            int c = lin >> 6, k = lin & 63;
            KVs[c][k] = Kg[(size_t)(j0 + c) * 512 + k];
        }
        __syncthreads();

        float s[16];
#pragma unroll
        for (int c = 0; c < 16; c++) s[c] = 0.f;
        for (int k = 0; k < 64; k++) {
            const float qv = Qs[r][k];
#pragma unroll
            for (int c = 0; c < 16; c++) s[c] += qv * KVs[hc * 16 + c][k];
        }

        float tmax = -1e30f;
#pragma unroll
        for (int c = 0; c < 16; c++) {
            const int j = j0 + hc * 16 + c;
            const bool ok = (j <= i) && (j >= i - WINDOW);
            s[c] = ok ? s[c] * 0.125f : -1e30f;
            tmax = fmaxf(tmax, s[c]);
        }
        tmax = fmaxf(tmax, __shfl_xor_sync(0xffffffffu, tmax, 1));
        const float mnew = fmaxf(m, tmax);
        const float scale = __expf(m - mnew);

        float psum = 0.f;
#pragma unroll
        for (int c = 0; c < 16; c++) {
            const float p = (s[c] > -1e29f) ? __expf(s[c] - mnew) : 0.f;
            Ps[r][hc * 16 + c] = p;
            psum += p;
        }
        l = l * scale + psum;
        m = mnew;
#pragma unroll
        for (int d = 0; d < 32; d++) o[d] *= scale;

        __syncthreads();

        for (int lin = tid; lin < 32 * 64; lin += 128) {
            int c = lin >> 6, k = lin & 63;
            KVs[c][k] = Vg[(size_t)(j0 + c) * 512 + k];
        }
        __syncthreads();

#pragma unroll 4
        for (int c = 0; c < 32; c++) {
            const float p = Ps[r][c];
#pragma unroll
            for (int d = 0; d < 32; d++) o[d] += p * KVs[c][hc * 32 + d];
        }
        __syncthreads();
    }

    float ltot = l + __shfl_xor_sync(0xffffffffu, l, 1);
    const float inv = 1.f / ltot;
    float* Og = g_O + ((size_t)(b * S + i)) * 1024 + h * 64 + hc * 32;
#pragma unroll
    for (int d = 0; d < 32; d++) Og[d] = o[d] * inv;
}

extern "C" void kernel_launch(void* const* d_in, const int* in_sizes, int n_in,
                              void* d_out, int out_size)
{
    const float* X  = (const float*)d_in[0];
    const float* Wq = (const float*)d_in[1];
    const float* Wk = (const float*)d_in[2];
    const float* Wv = (const float*)d_in[3];
    const float* Wo = (const float*)d_in[4];
    float* out = (float*)d_out;

    rope_init_kernel<<<256, 256>>>();
    qkv_tf32_kernel<<<dim3(16, 32), 256>>>(X, Wq, Wk, Wv);
    rope_apply_kernel<<<(M_TOT * 768) / 256, 256>>>();
    attn_kernel<<<dim3(S / 64, Bsz * H), 128>>>();
    outproj_tf32_kernel<<<dim3(8, 32), 256>>>(Wo, out);
}

// round 6
// speedup vs baseline: 2.0304x; 1.4034x over previous
#include <cuda_runtime.h>
#include <cuda_bf16.h>
#include <math.h>
#include <stdint.h>

#define Bsz 2
#define S 2048
#define H 16
#define KV 8
#define HD 64
#define WINDOW 512
#define M_TOT (Bsz * S)      // 4096

__device__ float g_Q[M_TOT * (H * HD)];    // [b*s, 1024]
__device__ float g_K[M_TOT * (KV * HD)];   // [b*s, 512]
__device__ float g_V[M_TOT * (KV * HD)];
__device__ float g_O[M_TOT * (H * HD)];
__device__ float2 g_rope[S * 32];          // (cos,sin) per (t,f)

__device__ __forceinline__ uint32_t f2tf(float f) {
    uint32_t r;
    asm("cvt.rna.tf32.f32 %0, %1;" : "=r"(r) : "f"(f));
    return r;
}

__device__ __forceinline__ void mma_tf32(float c[4],
    uint32_t a0, uint32_t a1, uint32_t a2, uint32_t a3, uint32_t b0, uint32_t b1) {
    asm volatile(
        "mma.sync.aligned.m16n8k8.row.col.f32.tf32.tf32.f32 "
        "{%0,%1,%2,%3}, {%4,%5,%6,%7}, {%8,%9}, {%0,%1,%2,%3};"
        : "+f"(c[0]), "+f"(c[1]), "+f"(c[2]), "+f"(c[3])
        : "r"(a0), "r"(a1), "r"(a2), "r"(a3), "r"(b0), "r"(b1));
}

// ---------------------------------------------------------------------------
// RoPE table + in-place apply
// ---------------------------------------------------------------------------
__global__ void rope_init_kernel() {
    const int idx = blockIdx.x * 256 + threadIdx.x;  // 65536
    const int t = idx >> 5, f = idx & 31;
    const float invf = expf(-logf(10000.0f) * (float)f * (1.0f / 32.0f));
    float sv, cv;
    sincosf((float)t * invf, &sv, &cv);
    g_rope[idx] = make_float2(cv, sv);
}

__global__ __launch_bounds__(256) void rope_apply_kernel() {
    const int idx = blockIdx.x * 256 + threadIdx.x;
    float* buf; int ld, p;
    if (idx < M_TOT * 512) { buf = g_Q; ld = 1024; p = idx; }
    else                   { buf = g_K; ld = 512;  p = idx - M_TOT * 512; }
    const int pph = ld >> 1;
    const int row = p / pph;
    const int q = p - row * pph;
    const int h = q >> 5, f = q & 31;
    const int t = row & (S - 1);
    float* base = buf + (size_t)row * ld + h * 64 + f;
    const float x = base[0], y = base[32];
    const float2 cs = g_rope[t * 32 + f];
    base[0]  = x * cs.x - y * cs.y;
    base[32] = y * cs.x + x * cs.y;
}

// ---------------------------------------------------------------------------
// tf32 GEMM core (unchanged from R4): 128x128 tile, BK=16, 256 threads
// ---------------------------------------------------------------------------
__device__ __forceinline__ void gemm_tf32_core(
    const float* __restrict__ A0,
    const float* __restrict__ Bp, int ldb, int colbase,
    uint2 (*sA)[2][512], uint2 (*sB)[2][512],
    float c[4][4][4])
{
    const int tid = threadIdx.x, lane = tid & 31, warp = tid >> 5;
    const int wm = warp >> 2, wn = warp & 3;

#pragma unroll
    for (int m = 0; m < 4; m++)
#pragma unroll
        for (int n = 0; n < 4; n++)
#pragma unroll
            for (int q = 0; q < 4; q++) c[m][n][q] = 0.f;

    const int am = tid >> 1, akc = tid & 1;
    const float* ap = A0 + (size_t)am * 1024 + akc * 8;
    const int bc = tid & 3, bkc = (tid >> 2) & 1, bn = (tid >> 3) * 4;
    const float* bp = Bp + (size_t)(bkc * 8 + bc) * ldb + colbase + bn;

    float la[8], lb[8];
#define LOAD_G(k0) do { \
        float4 a0_ = *(const float4*)(ap + (k0)); \
        float4 a1_ = *(const float4*)(ap + (k0) + 4); \
        la[0]=a0_.x; la[1]=a0_.y; la[2]=a0_.z; la[3]=a0_.w; \
        la[4]=a1_.x; la[5]=a1_.y; la[6]=a1_.z; la[7]=a1_.w; \
        float4 b0_ = *(const float4*)(bp + (size_t)(k0) * ldb); \
        float4 b1_ = *(const float4*)(bp + (size_t)((k0) + 4) * ldb); \
        lb[0]=b0_.x; lb[1]=b0_.y; lb[2]=b0_.z; lb[3]=b0_.w; \
        lb[4]=b1_.x; lb[5]=b1_.y; lb[6]=b1_.z; lb[7]=b1_.w; \
    } while (0)
#define STS_T(st) do { \
        uint2* a_ = sA[st][akc] + am * 4; \
        a_[0] = make_uint2(f2tf(la[0]), f2tf(la[4])); \
        a_[1] = make_uint2(f2tf(la[1]), f2tf(la[5])); \
        a_[2] = make_uint2(f2tf(la[2]), f2tf(la[6])); \
        a_[3] = make_uint2(f2tf(la[3]), f2tf(la[7])); \
        uint2* b_ = sB[st][bkc]; \
        b_[(bn + 0) * 4 + bc] = make_uint2(f2tf(lb[0]), f2tf(lb[4])); \
        b_[(bn + 1) * 4 + bc] = make_uint2(f2tf(lb[1]), f2tf(lb[5])); \
        b_[(bn + 2) * 4 + bc] = make_uint2(f2tf(lb[2]), f2tf(lb[6])); \
        b_[(bn + 3) * 4 + bc] = make_uint2(f2tf(lb[3]), f2tf(lb[7])); \
    } while (0)

    LOAD_G(0);
    STS_T(0);
    __syncthreads();

    for (int kt = 0; kt < 64; kt++) {
        const int st = kt & 1;
        if (kt < 63) LOAD_G((kt + 1) * 16);
#pragma unroll
        for (int kc = 0; kc < 2; kc++) {
            const uint2* a = sA[st][kc];
            const uint2* b = sB[st][kc];
            uint2 alo[4], ahi[4], bf[4];
#pragma unroll
            for (int m = 0; m < 4; m++) {
                alo[m] = a[wm * 256 + m * 64 + lane];
                ahi[m] = a[wm * 256 + m * 64 + 32 + lane];
            }
#pragma unroll
            for (int n = 0; n < 4; n++)
                bf[n] = b[wn * 128 + n * 32 + lane];
#pragma unroll
            for (int m = 0; m < 4; m++)
#pragma unroll
                for (int n = 0; n < 4; n++)
                    mma_tf32(c[m][n], alo[m].x, ahi[m].x, alo[m].y, ahi[m].y,
                             bf[n].x, bf[n].y);
        }
        if (kt < 63) STS_T(st ^ 1);
        __syncthreads();
    }
#undef LOAD_G
#undef STS_T
}

__device__ __forceinline__ void gemm_store(
    float* dst, int dld, int mrow0, int colbase, float c[4][4][4])
{
    const int lane = threadIdx.x & 31, warp = threadIdx.x >> 5;
    const int wm = warp >> 2, wn = warp & 3;
#pragma unroll
    for (int m = 0; m < 4; m++) {
        const int r0 = mrow0 + wm * 64 + m * 16 + (lane >> 2);
#pragma unroll
        for (int n = 0; n < 4; n++) {
            const int gc = colbase + wn * 32 + n * 8 + 2 * (lane & 3);
            *(float2*)&dst[(size_t)r0 * dld + gc]       = make_float2(c[m][n][0], c[m][n][1]);
            *(float2*)&dst[(size_t)(r0 + 8) * dld + gc] = make_float2(c[m][n][2], c[m][n][3]);
        }
    }
}

__global__ __launch_bounds__(256) void qkv_tf32_kernel(
    const float* __restrict__ X, const float* __restrict__ Wq,
    const float* __restrict__ Wk, const float* __restrict__ Wv)
{
    __shared__ uint2 sA[2][2][512];
    __shared__ uint2 sB[2][2][512];
    const int bx = blockIdx.x;
    const int mrow0 = blockIdx.y * 128;
    const float* Bp; int ldb; float* dst; int dld; int colbase;
    if (bx < 8)       { Bp = Wq; ldb = 1024; dst = g_Q; dld = 1024; colbase = bx * 128; }
    else if (bx < 12) { Bp = Wk; ldb = 512;  dst = g_K; dld = 512;  colbase = (bx - 8) * 128; }
    else              { Bp = Wv; ldb = 512;  dst = g_V; dld = 512;  colbase = (bx - 12) * 128; }
    float c[4][4][4];
    gemm_tf32_core(X + (size_t)mrow0 * 1024, Bp, ldb, colbase, sA, sB, c);
    gemm_store(dst, dld, mrow0, colbase, c);
}

__global__ __launch_bounds__(256) void outproj_tf32_kernel(
    const float* __restrict__ Wo, float* __restrict__ out)
{
    __shared__ uint2 sA[2][2][512];
    __shared__ uint2 sB[2][2][512];
    const int colbase = blockIdx.x * 128;
    const int mrow0 = blockIdx.y * 128;
    float c[4][4][4];
    gemm_tf32_core(g_O + (size_t)mrow0 * 1024, Wo, 1024, colbase, sA, sB, c);
    gemm_store(out, 1024, mrow0, colbase, c);
}

// ---------------------------------------------------------------------------
// Attention v2: 64x64 tiles, 256 threads, 4x4 register tiling, fp32.
// Qs/KVs staged transposed [d][row] -> QK^T inner step = 2x LDS.128 + 16 FFMA.
// PV: P staged in smem [row][key], V [key][d] -> 8x LDS.128 per 64 FFMA.
// smem = 3 * 16KB = 48KB exactly.
// ---------------------------------------------------------------------------
__global__ __launch_bounds__(256) void attn_kernel()
{
    __shared__ float Qs[64][64];    // [d][row], prescaled by 0.125
    __shared__ float KVs[64][64];   // K phase: [d][key]; V phase: [key][d]
    __shared__ float Ps[64][64];    // [row][key]

    const int bh = blockIdx.y;
    const int b = bh >> 4, h = bh & 15, kvh = h >> 1;
    const int q0 = blockIdx.x * 64;
    const int tid = threadIdx.x;
    const int tx = tid & 15, ty = tid >> 4;

    // load Q tile transposed + prescaled
    {
        const int rr = tid >> 2;
        const int d0 = (tid & 3) * 16;
        const float* Qg = g_Q + ((size_t)(b * S + q0 + rr)) * 1024 + h * 64 + d0;
#pragma unroll
        for (int u = 0; u < 4; u++) {
            float4 v = *(const float4*)(Qg + 4 * u);
            Qs[d0 + 4 * u + 0][rr] = v.x * 0.125f;
            Qs[d0 + 4 * u + 1][rr] = v.y * 0.125f;
            Qs[d0 + 4 * u + 2][rr] = v.z * 0.125f;
            Qs[d0 + 4 * u + 3][rr] = v.w * 0.125f;
        }
    }

    float o[4][4];
#pragma unroll
    for (int i = 0; i < 4; i++)
#pragma unroll
        for (int j = 0; j < 4; j++) o[i][j] = 0.f;
    float mrow[4] = {-1e30f, -1e30f, -1e30f, -1e30f};
    float lrow[4] = {0.f, 0.f, 0.f, 0.f};

    const int t0 = max(0, q0 - WINDOW) >> 6;
    const int t1 = q0 >> 6;
    const bool hasLeft = (q0 >= WINDOW);

    for (int t = t0; t <= t1; t++) {
        const int j0 = t << 6;

        // load K tile transposed
        {
            const int cc = tid >> 2;
            const int d0 = (tid & 3) * 16;
            const float* Kg = g_K + ((size_t)(b * S + j0 + cc)) * 512 + kvh * 64 + d0;
#pragma unroll
            for (int u = 0; u < 4; u++) {
                float4 v = *(const float4*)(Kg + 4 * u);
                KVs[d0 + 4 * u + 0][cc] = v.x;
                KVs[d0 + 4 * u + 1][cc] = v.y;
                KVs[d0 + 4 * u + 2][cc] = v.z;
                KVs[d0 + 4 * u + 3][cc] = v.w;
            }
        }
        __syncthreads();

        // S = (Q/8) K^T
        float s[4][4];
#pragma unroll
        for (int i = 0; i < 4; i++)
#pragma unroll
            for (int j = 0; j < 4; j++) s[i][j] = 0.f;
#pragma unroll 4
        for (int k = 0; k < 64; k++) {
            const float4 a = *(const float4*)&Qs[k][4 * ty];
            const float4 v = *(const float4*)&KVs[k][4 * tx];
            const float av[4] = {a.x, a.y, a.z, a.w};
            const float bv[4] = {v.x, v.y, v.z, v.w};
#pragma unroll
            for (int i = 0; i < 4; i++)
#pragma unroll
                for (int j = 0; j < 4; j++) s[i][j] += av[i] * bv[j];
        }

        const bool causalEdge = (t == t1);
        const bool leftEdge = hasLeft && (t == t0);

        // online softmax per owned row
#pragma unroll
        for (int i = 0; i < 4; i++) {
            const int r = 4 * ty + i;
            if (causalEdge) {
#pragma unroll
                for (int j = 0; j < 4; j++)
                    if (4 * tx + j > r) s[i][j] = -1e30f;
            }
            if (leftEdge) {
#pragma unroll
                for (int j = 0; j < 4; j++)
                    if (4 * tx + j < r) s[i][j] = -1e30f;
            }
            float rm = fmaxf(fmaxf(s[i][0], s[i][1]), fmaxf(s[i][2], s[i][3]));
            rm = fmaxf(rm, __shfl_xor_sync(0xffffffffu, rm, 1));
            rm = fmaxf(rm, __shfl_xor_sync(0xffffffffu, rm, 2));
            rm = fmaxf(rm, __shfl_xor_sync(0xffffffffu, rm, 4));
            rm = fmaxf(rm, __shfl_xor_sync(0xffffffffu, rm, 8));
            const float mn = fmaxf(mrow[i], rm);
            const float sc = __expf(mrow[i] - mn);
            mrow[i] = mn;
            float ps = 0.f;
#pragma unroll
            for (int j = 0; j < 4; j++) {
                const float p = __expf(s[i][j] - mn);
                s[i][j] = p;
                ps += p;
            }
            ps += __shfl_xor_sync(0xffffffffu, ps, 1);
            ps += __shfl_xor_sync(0xffffffffu, ps, 2);
            ps += __shfl_xor_sync(0xffffffffu, ps, 4);
            ps += __shfl_xor_sync(0xffffffffu, ps, 8);
            lrow[i] = lrow[i] * sc + ps;
#pragma unroll
            for (int j = 0; j < 4; j++) o[i][j] *= sc;
            *(float4*)&Ps[r][4 * tx] = make_float4(s[i][0], s[i][1], s[i][2], s[i][3]);
        }
        __syncthreads();   // Ps visible; K reads done

        // load V tile [key][d]
        {
            const int cc = tid >> 2;
            const int d0 = (tid & 3) * 16;
            const float* Vg = g_V + ((size_t)(b * S + j0 + cc)) * 512 + kvh * 64 + d0;
#pragma unroll
            for (int u = 0; u < 4; u++)
                *(float4*)&KVs[cc][d0 + 4 * u] = *(const float4*)(Vg + 4 * u);
        }
        __syncthreads();

        // O += P V
#pragma unroll 2
        for (int c0 = 0; c0 < 64; c0 += 4) {
            float4 pv[4];
#pragma unroll
            for (int i = 0; i < 4; i++)
                pv[i] = *(const float4*)&Ps[4 * ty + i][c0];
#pragma unroll
            for (int cc = 0; cc < 4; cc++) {
                const float4 v = *(const float4*)&KVs[c0 + cc][4 * tx];
                const float vv[4] = {v.x, v.y, v.z, v.w};
                const float pc[4] = {((const float*)&pv[0])[cc], ((const float*)&pv[1])[cc],
                                     ((const float*)&pv[2])[cc], ((const float*)&pv[3])[cc]};
#pragma unroll
                for (int i = 0; i < 4; i++)
#pragma unroll
                    for (int j = 0; j < 4; j++)
                        o[i][j] += pc[i] * vv[j];
            }
        }
        __syncthreads();   // before next tile overwrites KVs/Ps
    }

    // write O
#pragma unroll
    for (int i = 0; i < 4; i++) {
        const float inv = 1.f / lrow[i];
        float* Og = g_O + ((size_t)(b * S + q0 + 4 * ty + i)) * 1024 + h * 64 + 4 * tx;
        *(float4*)Og = make_float4(o[i][0] * inv, o[i][1] * inv, o[i][2] * inv, o[i][3] * inv);
    }
}

extern "C" void kernel_launch(void* const* d_in, const int* in_sizes, int n_in,
                              void* d_out, int out_size)
{
    const float* X  = (const float*)d_in[0];
    const float* Wq = (const float*)d_in[1];
    const float* Wk = (const float*)d_in[2];
    const float* Wv = (const float*)d_in[3];
    const float* Wo = (const float*)d_in[4];
    float* out = (float*)d_out;

    rope_init_kernel<<<256, 256>>>();
    qkv_tf32_kernel<<<dim3(16, 32), 256>>>(X, Wq, Wk, Wv);
    rope_apply_kernel<<<(M_TOT * 768) / 256, 256>>>();
    attn_kernel<<<dim3(S / 64, Bsz * H), 256>>>();
    outproj_tf32_kernel<<<dim3(8, 32), 256>>>(Wo, out);
}